// round 7
// baseline (speedup 1.0000x reference)
#include <cuda_runtime.h>
#include <cuda.h>
#include <cstdint>

// ---------------- problem constants ----------------
#define NN     10000
#define NPAD   10016
#define CC     128
#define NADJ   3
#define NSLOPE 0.2f

#define KCH     32
#define NCHUNK  ((NN + KCH - 1) / KCH)      // 313
#define NSPLIT  11
#define MTILES  ((NN + 127) / 128)          // 79
#define MPAD    (MTILES * 128)

#define BTILE_BYTES 16384                   // 128 x 32 fp32
#define STAGES_B    4
#define MIX_BYTES   16384
#define DYNSMEM     (STAGES_B * BTILE_BYTES + 2 * MIX_BYTES + 1024)

// scratch (static device arrays — zero-initialized, no allocation)
__device__ __align__(1024) float g_sup_t[CC * NPAD];           // supᵀ tf32, rotated layout
__device__ __align__(16)   float g_part[NSPLIT][MPAD][CC];     // split-K partials

// ---------------- helpers ----------------
__device__ __forceinline__ uint32_t smem_u32(const void* p) {
    uint32_t a;
    asm("{ .reg .u64 t; cvta.to.shared.u64 t, %1; cvt.u32.u64 %0, t; }" : "=r"(a) : "l"(p));
    return a;
}
__device__ __forceinline__ float tf32_rna_f(float x) {
    uint32_t u;
    asm("cvt.rna.tf32.f32 %0, %1;" : "=r"(u) : "f"(x));
    return __uint_as_float(u);
}
__device__ __forceinline__ uint32_t f2tf32(float x) {
    uint32_t u;
    asm("cvt.rna.tf32.f32 %0, %1;" : "=r"(u) : "f"(x));
    return u;
}
__device__ __forceinline__ void lds_b64(uint32_t a, uint32_t& lo, uint32_t& hi) {
    asm volatile("ld.shared.v2.b32 {%0, %1}, [%2];" : "=r"(lo), "=r"(hi) : "r"(a));
}
__device__ __forceinline__ void sts_b64(uint32_t a, uint32_t lo, uint32_t hi) {
    asm volatile("st.shared.v2.b32 [%0], {%1, %2};" :: "r"(a), "r"(lo), "r"(hi) : "memory");
}

#define MBARRIER_INIT(addr, cnt) \
    asm volatile("mbarrier.init.shared.b64 [%0], %1;" :: "r"(addr), "r"(cnt) : "memory")
#define MBARRIER_EXPECT_TX(addr, bytes) \
    asm volatile("mbarrier.arrive.expect_tx.shared.b64 _, [%0], %1;" :: "r"(addr), "r"(bytes) : "memory")
#define MBARRIER_ARRIVE(addr) \
    asm volatile("mbarrier.arrive.shared.b64 _, [%0];" :: "r"(addr) : "memory")

#define MBARRIER_WAIT_PARITY(mbar, par) do {                                      \
    uint32_t _m = (mbar), _p = (par), _d;                                         \
    asm volatile("{\n\t.reg .pred p;\n\t"                                         \
        "mbarrier.try_wait.parity.acquire.cta.shared::cta.b64 p, [%1], %2;\n\t"   \
        "selp.b32 %0, 1, 0, p;\n\t}" : "=r"(_d) : "r"(_m), "r"(_p) : "memory");   \
    if (!_d) {                                                                    \
        asm volatile("{\n\t.reg .pred P1;\n\t"                                    \
            "W_%=:\n\t"                                                           \
            "mbarrier.try_wait.parity.acquire.cta.shared::cta.b64 P1, [%0], %1, 0x989680;\n\t" \
            "@P1 bra.uni D_%=;\n\t"                                               \
            "bra.uni W_%=;\n\t"                                                   \
            "D_%=:\n\t}" :: "r"(_m), "r"(_p) : "memory");                         \
    } } while (0)

#define MBARRIER_WAIT_PARITY_RELAXED(mbar, par) do {                              \
    uint32_t _m = (mbar), _p = (par), _d;                                         \
    asm volatile("{\n\t.reg .pred p;\n\t"                                         \
        "mbarrier.try_wait.parity.relaxed.cta.shared::cta.b64 p, [%1], %2, 0x989680;\n\t" \
        "selp.b32 %0, 1, 0, p;\n\t}" : "=r"(_d) : "r"(_m), "r"(_p) : "memory");   \
    if (!_d) {                                                                    \
        asm volatile("{\n\t.reg .pred P1;\n\t"                                    \
            "W_%=:\n\t"                                                           \
            "mbarrier.try_wait.parity.relaxed.cta.shared::cta.b64 P1, [%0], %1, 0x989680;\n\t" \
            "@P1 bra.uni D_%=;\n\t"                                               \
            "bra.uni W_%=;\n\t"                                                   \
            "D_%=:\n\t}" :: "r"(_m), "r"(_p) : "memory");                         \
    } } while (0)

#define TMA_LOAD_3D(sa, tmap, x, y, z, mbar)                                      \
    asm volatile("cp.async.bulk.tensor.3d.shared::cta.global.tile.mbarrier::complete_tx::bytes " \
        "[%0], [%1, {%2, %3, %4}], [%5];"                                         \
        :: "r"((uint32_t)(sa)), "l"(tmap), "r"((int)(x)), "r"((int)(y)),          \
           "r"((int)(z)), "r"((uint32_t)(mbar)) : "memory")

// mma.sync m16n8k8 tf32 (baseline PTX)
__device__ __forceinline__ void mma_tf32(float* c, const uint32_t* A,
                                         uint32_t b0, uint32_t b1) {
    asm volatile(
        "mma.sync.aligned.m16n8k8.row.col.f32.tf32.tf32.f32 "
        "{%0,%1,%2,%3}, {%4,%5,%6,%7}, {%8,%9}, {%0,%1,%2,%3};"
        : "+f"(c[0]), "+f"(c[1]), "+f"(c[2]), "+f"(c[3])
        : "r"(A[0]), "r"(A[1]), "r"(A[2]), "r"(A[3]), "r"(b0), "r"(b1));
}

// ---------------- kernel 1: support = X@W + b ; rotated transposed tf32 copy -------
__global__ void __launch_bounds__(128)
k_support(const float* __restrict__ inp, const float* __restrict__ w,
          const float* __restrict__ b) {
    __shared__ float in_s[8][CC];
    __shared__ float s_out[CC][9];
    const int t  = threadIdx.x;
    const int n0 = blockIdx.x * 8;

    #pragma unroll
    for (int j = 0; j < 8; ++j)
        in_s[j][t] = inp[(n0 + j) * CC + t];
    __syncthreads();

    float acc[8];
    #pragma unroll
    for (int j = 0; j < 8; ++j) acc[j] = 0.f;
    const float bc = b[t];
    #pragma unroll 4
    for (int i = 0; i < CC; ++i) {
        const float wv = w[i * CC + t];
        #pragma unroll
        for (int j = 0; j < 8; ++j) acc[j] = fmaf(in_s[j][i], wv, acc[j]);
    }
    #pragma unroll
    for (int j = 0; j < 8; ++j) s_out[t][j] = acc[j] + bc;
    __syncthreads();

    const int j2 = t & 7;
    const int c0 = t >> 3;
    const int nloc  = (n0 & 31) | j2;
    const int ks    = nloc >> 3;
    const int p     = nloc & 3;
    const int hi    = (nloc >> 2) & 1;
    const int nbase = n0 & ~31;
    #pragma unroll
    for (int cc = 0; cc < CC; cc += 16) {
        const int c = cc + c0;
        const int perm = (((ks + c) & 3) << 3) | ((2 * p + 2 * c) & 6) | hi;
        g_sup_t[c * NPAD + nbase + perm] = tf32_rna_f(s_out[c][j2]);
    }
}

// ---------------- kernel 2: warp-specialized split-K tf32 HMMA GEMM ----------------
// warps 0-7: MMA consumers (4M x 2N, 32x64 each).  warps 8-15: premix producers.
__global__ void __launch_bounds__(512, 1)
k_gemm(const __grid_constant__ CUtensorMap tmap_b,
       const float* __restrict__ adj,
       const float* __restrict__ att) {
    extern __shared__ __align__(1024) char dsm[];
    __shared__ __align__(8) uint64_t bars[2 * STAGES_B + 4];

    const int tid  = threadIdx.x;
    const int wid  = tid >> 5;
    const int lane = tid & 31;
    const int g    = lane >> 2;
    const int q    = lane & 3;
    const int m0   = blockIdx.x * 128;
    const int sidx = blockIdx.y;

    const uint32_t dbase   = (smem_u32(dsm) + 1023u) & ~1023u;
    const uint32_t mixbase = dbase + STAGES_B * BTILE_BYTES;
    const uint32_t barb    = smem_u32(bars);
    // Bfull[s]: barb+8s   Bempty[s]: barb+8(4+s)   mfull[b]: barb+8(8+b)   mempty[b]: barb+8(10+b)
    const uint32_t Bfull  = barb;
    const uint32_t Bempty = barb + 8 * STAGES_B;
    const uint32_t mfull  = barb + 8 * (2 * STAGES_B);
    const uint32_t mempty = barb + 8 * (2 * STAGES_B + 2);

    if (tid == 0) {
        for (int s = 0; s < STAGES_B; ++s) {
            MBARRIER_INIT(Bfull + 8 * s, 1);
            MBARRIER_INIT(Bempty + 8 * s, 256);
        }
        for (int b2 = 0; b2 < 2; ++b2) {
            MBARRIER_INIT(mfull + 8 * b2, 256);
            MBARRIER_INIT(mempty + 8 * b2, 256);
        }
        asm volatile("fence.proxy.async.shared::cta;" ::: "memory");
    }
    __syncthreads();   // only CTA-wide sync; after this, producer/consumer run free

    const int nch = (NCHUNK - sidx + NSPLIT - 1) / NSPLIT;

    if (wid >= 8) {
        // ================= PRODUCERS =================
        const float at0 = att[0], at1 = att[1], at2 = att[2];
        const int ptid = tid - 256;            // 0..255
        const int r    = ptid >> 1;            // row 0..127
        const int h    = ptid & 1;             // k-half: k in [16h, 16h+16)
        const int mrow = (m0 + r < NN) ? (m0 + r) : (NN - 1);
        const float* arow = adj + (size_t)mrow * NN + 16 * h;
        // STS bases for the 2 owned blocks ks = 2h+0, 2h+1
        const uint32_t sbase0 = (uint32_t)r * 32 + (uint32_t)(((2 * h + 0 + r) & 3) << 3);
        const uint32_t sbase1 = (uint32_t)r * 32 + (uint32_t)(((2 * h + 1 + r) & 3) << 3);
        const uint32_t srot   = (uint32_t)(2 * r);

        // TMA B prologue (single thread)
        if (tid == 511) {
            int pre = (nch < STAGES_B) ? nch : STAGES_B;
            for (int i = 0; i < pre; ++i) {
                MBARRIER_EXPECT_TX(Bfull + 8 * i, (uint32_t)BTILE_BYTES);
                TMA_LOAD_3D(dbase + i * BTILE_BYTES, &tmap_b,
                            (sidx + i * NSPLIT) * KCH, 0, 0, Bfull + 8 * i);
            }
        }

        // prefetch chunk 0
        float4 pf[NADJ][4];
        {
            const int k0 = sidx * KCH;
            const bool ok = (k0 + 16 * h + 16 <= NN);
            #pragma unroll
            for (int t = 0; t < NADJ; ++t) {
                const float* p0 = arow + (size_t)t * NN * NN + k0;
                #pragma unroll
                for (int j = 0; j < 4; ++j)
                    pf[t][j] = ok ? *reinterpret_cast<const float4*>(p0 + 4 * j)
                                  : make_float4(0.f, 0.f, 0.f, 0.f);
            }
        }

        for (int j = 0; j < nch; ++j) {
            // premix 16 values in registers
            float mv[16];
            #pragma unroll
            for (int i = 0; i < 16; ++i) {
                const float x = (&pf[0][i >> 2].x)[i & 3];
                const float y = (&pf[1][i >> 2].x)[i & 3];
                const float z = (&pf[2][i >> 2].x)[i & 3];
                mv[i] = fmaf(at2, z, fmaf(at1, y, at0 * x));
            }

            if (j >= 2) MBARRIER_WAIT_PARITY(mempty + 8 * (j & 1), ((j >> 1) + 1) & 1);
            const uint32_t mixb = mixbase + (uint32_t)(j & 1) * MIX_BYTES;
            #pragma unroll
            for (int p = 0; p < 4; ++p) {
                const uint32_t slot = (srot + 2 * (uint32_t)p) & 6;
                sts_b64(mixb + (sbase0 + slot) * 4, f2tf32(mv[p]),     f2tf32(mv[p + 4]));
                sts_b64(mixb + (sbase1 + slot) * 4, f2tf32(mv[p + 8]), f2tf32(mv[p + 12]));
            }
            MBARRIER_ARRIVE(mfull + 8 * (j & 1));

            // prefetch next chunk
            if (j + 1 < nch) {
                const int k0n = (sidx + (j + 1) * NSPLIT) * KCH;
                const bool ok = (k0n + 16 * h + 16 <= NN);
                #pragma unroll
                for (int t = 0; t < NADJ; ++t) {
                    const float* p0 = arow + (size_t)t * NN * NN + k0n;
                    #pragma unroll
                    for (int jj = 0; jj < 4; ++jj)
                        pf[t][jj] = ok ? *reinterpret_cast<const float4*>(p0 + 4 * jj)
                                       : make_float4(0.f, 0.f, 0.f, 0.f);
                }
            }

            // B ring refill
            if (tid == 511 && j + STAGES_B < nch) {
                const int s = j & (STAGES_B - 1);    // (j+4)%4 == j%4
                MBARRIER_WAIT_PARITY_RELAXED(Bempty + 8 * s, (j / STAGES_B) & 1);
                MBARRIER_EXPECT_TX(Bfull + 8 * s, (uint32_t)BTILE_BYTES);
                TMA_LOAD_3D(dbase + s * BTILE_BYTES, &tmap_b,
                            (sidx + (j + STAGES_B) * NSPLIT) * KCH, 0, 0, Bfull + 8 * s);
            }
        }
    } else {
        // ================= CONSUMERS =================
        const int wm = wid & 3;                // M sub-tile (32 rows)
        const int wn = wid >> 2;               // N sub-tile (64 cols)

        float acc[2][8][4];
        #pragma unroll
        for (int mi = 0; mi < 2; ++mi)
            #pragma unroll
            for (int ni = 0; ni < 8; ++ni)
                #pragma unroll
                for (int rr = 0; rr < 4; ++rr) acc[mi][ni][rr] = 0.f;

        for (int it = 0; it < nch; ++it) {
            const int s = it & (STAGES_B - 1);
            MBARRIER_WAIT_PARITY(mfull + 8 * (it & 1), (it >> 1) & 1);
            MBARRIER_WAIT_PARITY(Bfull + 8 * s, (it / STAGES_B) & 1);

            const uint32_t Bb   = dbase + s * BTILE_BYTES;
            const uint32_t mixb = mixbase + (uint32_t)(it & 1) * MIX_BYTES;

            #pragma unroll
            for (int ks = 0; ks < 4; ++ks) {
                const uint32_t koff = (uint32_t)(((((ks + g) & 3) << 3)) | ((2 * q + 2 * g) & 6));
                uint32_t amix[2][4];
                #pragma unroll
                for (int mi = 0; mi < 2; ++mi) {
                    const uint32_t wa = ((uint32_t)(wm * 32 + mi * 16 + g) * 32) + koff;
                    lds_b64(mixb + wa * 4,         amix[mi][0], amix[mi][2]);
                    lds_b64(mixb + (wa + 256) * 4, amix[mi][1], amix[mi][3]);
                }
                const uint32_t kb = koff ^ ((uint32_t)g << 2);
                #pragma unroll
                for (int ni = 0; ni < 8; ++ni) {
                    const uint32_t wb = ((uint32_t)(wn * 64 + ni * 8 + g) * 32) + kb;
                    uint32_t b0, b1;
                    lds_b64(Bb + wb * 4, b0, b1);
                    mma_tf32(acc[0][ni], amix[0], b0, b1);
                    mma_tf32(acc[1][ni], amix[1], b0, b1);
                }
            }

            MBARRIER_ARRIVE(mempty + 8 * (it & 1));
            MBARRIER_ARRIVE(Bempty + 8 * s);
        }

        // ---- write split-K partials ----
        float* pbase = &g_part[sidx][0][0];
        #pragma unroll
        for (int mi = 0; mi < 2; ++mi) {
            #pragma unroll
            for (int ni = 0; ni < 8; ++ni) {
                const int r = m0 + wm * 32 + mi * 16 + g;
                const int c = wn * 64 + ni * 8 + q * 2;
                float2 v0 = make_float2(acc[mi][ni][0], acc[mi][ni][1]);
                float2 v1 = make_float2(acc[mi][ni][2], acc[mi][ni][3]);
                *reinterpret_cast<float2*>(pbase + (size_t)r * CC + c)       = v0;
                *reinterpret_cast<float2*>(pbase + (size_t)(r + 8) * CC + c) = v1;
            }
        }
    }
}

// ---------------- kernel 3: reduce split-K partials + LeakyReLU --------------------
__global__ void __launch_bounds__(256)
k_reduce(float* __restrict__ out) {
    const int idx = blockIdx.x * 256 + threadIdx.x;
    const int total = NN * CC / 4;
    if (idx >= total) return;
    const int n  = idx / (CC / 4);
    const int c4 = (idx % (CC / 4)) * 4;

    float4 s = make_float4(0.f, 0.f, 0.f, 0.f);
    #pragma unroll
    for (int k = 0; k < NSPLIT; ++k) {
        const float4 v = *reinterpret_cast<const float4*>(&g_part[k][n][c4]);
        s.x += v.x; s.y += v.y; s.z += v.z; s.w += v.w;
    }
    s.x = (s.x >= 0.f) ? s.x : NSLOPE * s.x;
    s.y = (s.y >= 0.f) ? s.y : NSLOPE * s.y;
    s.z = (s.z >= 0.f) ? s.z : NSLOPE * s.z;
    s.w = (s.w >= 0.f) ? s.w : NSLOPE * s.w;
    *reinterpret_cast<float4*>(&out[(size_t)n * CC + c4]) = s;
}

// dummies: position k_gemm as 4th launch (6th overall) so ncu -s 5 -c 1 profiles it
__global__ void k_dummy() {}
__global__ void k_dummy2() {}

// ---------------- host launch ----------------
typedef CUresult (*PFN_encodeTiled)(
    CUtensorMap*, CUtensorMapDataType, cuuint32_t, void*,
    const cuuint64_t*, const cuuint64_t*, const cuuint32_t*, const cuuint32_t*,
    CUtensorMapInterleave, CUtensorMapSwizzle, CUtensorMapL2promotion,
    CUtensorMapFloatOOBfill);

extern "C" void kernel_launch(void* const* d_in, const int* in_sizes, int n_in,
                              void* d_out, int out_size) {
    const float *inp = nullptr, *adj = nullptr, *att = nullptr, *w = nullptr, *b = nullptr;
    for (int i = 0; i < n_in; ++i) {
        switch (in_sizes[i]) {
            case NN * CC:        inp = (const float*)d_in[i]; break;
            case NADJ * NN * NN: adj = (const float*)d_in[i]; break;
            case NADJ:           att = (const float*)d_in[i]; break;
            case CC * CC:        w   = (const float*)d_in[i]; break;
            case CC:             b   = (const float*)d_in[i]; break;
            default: break;
        }
    }
    float* out = (float*)d_out;

    k_support<<<NN / 8, 128>>>(inp, w, b);
    k_dummy<<<1, 32>>>();
    k_dummy2<<<1, 32>>>();

    PFN_encodeTiled enc = nullptr;
    {
        void* p = nullptr;
        cudaDriverEntryPointQueryResult st;
#if CUDART_VERSION >= 12050
        cudaGetDriverEntryPointByVersion("cuTensorMapEncodeTiled", &p, 12000,
                                         cudaEnableDefault, &st);
#else
        cudaGetDriverEntryPoint("cuTensorMapEncodeTiled", &p, cudaEnableDefault, &st);
#endif
        enc = (PFN_encodeTiled)p;
    }
    void* supt_ptr = nullptr;
    cudaGetSymbolAddress(&supt_ptr, g_sup_t);

    CUtensorMap tb;
    cuuint32_t box[3] = {KCH, 128, 1};
    cuuint32_t es[3]  = {1, 1, 1};
    {   // B: g_sup_t [CC][NPAD] (rotated layout), inner dim = K
        cuuint64_t dims[3] = {NPAD, CC, 1};
        cuuint64_t str[2]  = {(cuuint64_t)NPAD * 4, (cuuint64_t)CC * NPAD * 4};
        enc(&tb, CU_TENSOR_MAP_DATA_TYPE_FLOAT32, 3, supt_ptr, dims, str, box, es,
            CU_TENSOR_MAP_INTERLEAVE_NONE, CU_TENSOR_MAP_SWIZZLE_128B,
            CU_TENSOR_MAP_L2_PROMOTION_L2_128B, CU_TENSOR_MAP_FLOAT_OOB_FILL_NONE);
    }

    cudaFuncSetAttribute(k_gemm, cudaFuncAttributeMaxDynamicSharedMemorySize, DYNSMEM);
    dim3 grid(MTILES, NSPLIT);
    k_gemm<<<grid, 512, DYNSMEM>>>(tb, adj, att);

    k_reduce<<<(NN * CC / 4 + 255) / 256, 256>>>(out);
}

// round 8
// speedup vs baseline: 1.6222x; 1.6222x over previous
#include <cuda_runtime.h>
#include <cuda.h>
#include <cstdint>

// ---------------- problem constants ----------------
#define NN     10000
#define NPAD   10016
#define CC     128
#define NADJ   3
#define NSLOPE 0.2f

#define KCH     32
#define NCHUNK  ((NN + KCH - 1) / KCH)      // 313
#define NSPLIT  11
#define MTILES  ((NN + 127) / 128)          // 79
#define MPAD    (MTILES * 128)

#define BTILE_BYTES 16384                   // 128 x 32 fp32
#define STAGES_B    4
#define MIX_BYTES   16384
#define DYNSMEM     (STAGES_B * BTILE_BYTES + 2 * MIX_BYTES + 1024)

// scratch (static device arrays — zero-initialized, no allocation)
__device__ __align__(1024) float g_sup_t[CC * NPAD];           // supᵀ tf32, rotated layout
__device__ __align__(16)   float g_part[NSPLIT][MPAD][CC];     // split-K partials

// ---------------- helpers ----------------
__device__ __forceinline__ uint32_t smem_u32(const void* p) {
    uint32_t a;
    asm("{ .reg .u64 t; cvta.to.shared.u64 t, %1; cvt.u32.u64 %0, t; }" : "=r"(a) : "l"(p));
    return a;
}
__device__ __forceinline__ float tf32_rna_f(float x) {
    uint32_t u;
    asm("cvt.rna.tf32.f32 %0, %1;" : "=r"(u) : "f"(x));
    return __uint_as_float(u);
}
__device__ __forceinline__ uint32_t f2tf32(float x) {
    uint32_t u;
    asm("cvt.rna.tf32.f32 %0, %1;" : "=r"(u) : "f"(x));
    return u;
}
__device__ __forceinline__ void lds_b64(uint32_t a, uint32_t& lo, uint32_t& hi) {
    asm volatile("ld.shared.v2.b32 {%0, %1}, [%2];" : "=r"(lo), "=r"(hi) : "r"(a));
}
__device__ __forceinline__ void sts_b64(uint32_t a, uint32_t lo, uint32_t hi) {
    asm volatile("st.shared.v2.b32 [%0], {%1, %2};" :: "r"(a), "r"(lo), "r"(hi) : "memory");
}

#define MBARRIER_INIT(addr, cnt) \
    asm volatile("mbarrier.init.shared.b64 [%0], %1;" :: "r"(addr), "r"(cnt) : "memory")
#define MBARRIER_EXPECT_TX(addr, bytes) \
    asm volatile("mbarrier.arrive.expect_tx.shared.b64 _, [%0], %1;" :: "r"(addr), "r"(bytes) : "memory")
#define MBARRIER_ARRIVE(addr) \
    asm volatile("mbarrier.arrive.shared.b64 _, [%0];" :: "r"(addr) : "memory")

#define MBARRIER_WAIT_PARITY(mbar, par) do {                                      \
    uint32_t _m = (mbar), _p = (par), _d;                                         \
    asm volatile("{\n\t.reg .pred p;\n\t"                                         \
        "mbarrier.try_wait.parity.acquire.cta.shared::cta.b64 p, [%1], %2;\n\t"   \
        "selp.b32 %0, 1, 0, p;\n\t}" : "=r"(_d) : "r"(_m), "r"(_p) : "memory");   \
    if (!_d) {                                                                    \
        asm volatile("{\n\t.reg .pred P1;\n\t"                                    \
            "W_%=:\n\t"                                                           \
            "mbarrier.try_wait.parity.acquire.cta.shared::cta.b64 P1, [%0], %1, 0x989680;\n\t" \
            "@P1 bra.uni D_%=;\n\t"                                               \
            "bra.uni W_%=;\n\t"                                                   \
            "D_%=:\n\t}" :: "r"(_m), "r"(_p) : "memory");                         \
    } } while (0)

#define MBARRIER_WAIT_PARITY_RELAXED(mbar, par) do {                              \
    uint32_t _m = (mbar), _p = (par), _d;                                         \
    asm volatile("{\n\t.reg .pred p;\n\t"                                         \
        "mbarrier.try_wait.parity.relaxed.cta.shared::cta.b64 p, [%1], %2, 0x989680;\n\t" \
        "selp.b32 %0, 1, 0, p;\n\t}" : "=r"(_d) : "r"(_m), "r"(_p) : "memory");   \
    if (!_d) {                                                                    \
        asm volatile("{\n\t.reg .pred P1;\n\t"                                    \
            "W_%=:\n\t"                                                           \
            "mbarrier.try_wait.parity.relaxed.cta.shared::cta.b64 P1, [%0], %1, 0x989680;\n\t" \
            "@P1 bra.uni D_%=;\n\t"                                               \
            "bra.uni W_%=;\n\t"                                                   \
            "D_%=:\n\t}" :: "r"(_m), "r"(_p) : "memory");                         \
    } } while (0)

#define TMA_LOAD_3D(sa, tmap, x, y, z, mbar)                                      \
    asm volatile("cp.async.bulk.tensor.3d.shared::cta.global.tile.mbarrier::complete_tx::bytes " \
        "[%0], [%1, {%2, %3, %4}], [%5];"                                         \
        :: "r"((uint32_t)(sa)), "l"(tmap), "r"((int)(x)), "r"((int)(y)),          \
           "r"((int)(z)), "r"((uint32_t)(mbar)) : "memory")

// mma.sync m16n8k8 tf32 (baseline PTX)
__device__ __forceinline__ void mma_tf32(float* c, const uint32_t* A,
                                         uint32_t b0, uint32_t b1) {
    asm volatile(
        "mma.sync.aligned.m16n8k8.row.col.f32.tf32.tf32.f32 "
        "{%0,%1,%2,%3}, {%4,%5,%6,%7}, {%8,%9}, {%0,%1,%2,%3};"
        : "+f"(c[0]), "+f"(c[1]), "+f"(c[2]), "+f"(c[3])
        : "r"(A[0]), "r"(A[1]), "r"(A[2]), "r"(A[3]), "r"(b0), "r"(b1));
}

// ---------------- kernel 1: support = X@W + b ; rotated transposed tf32 copy -------
__global__ void __launch_bounds__(128)
k_support(const float* __restrict__ inp, const float* __restrict__ w,
          const float* __restrict__ b) {
    __shared__ float in_s[8][CC];
    __shared__ float s_out[CC][9];
    const int t  = threadIdx.x;
    const int n0 = blockIdx.x * 8;

    #pragma unroll
    for (int j = 0; j < 8; ++j)
        in_s[j][t] = inp[(n0 + j) * CC + t];
    __syncthreads();

    float acc[8];
    #pragma unroll
    for (int j = 0; j < 8; ++j) acc[j] = 0.f;
    const float bc = b[t];
    #pragma unroll 4
    for (int i = 0; i < CC; ++i) {
        const float wv = w[i * CC + t];
        #pragma unroll
        for (int j = 0; j < 8; ++j) acc[j] = fmaf(in_s[j][i], wv, acc[j]);
    }
    #pragma unroll
    for (int j = 0; j < 8; ++j) s_out[t][j] = acc[j] + bc;
    __syncthreads();

    const int j2 = t & 7;
    const int c0 = t >> 3;
    const int nloc  = (n0 & 31) | j2;
    const int ks    = nloc >> 3;
    const int p     = nloc & 3;
    const int hi    = (nloc >> 2) & 1;
    const int nbase = n0 & ~31;
    #pragma unroll
    for (int cc = 0; cc < CC; cc += 16) {
        const int c = cc + c0;
        const int perm = (((ks + c) & 3) << 3) | ((2 * p + 2 * c) & 6) | hi;
        g_sup_t[c * NPAD + nbase + perm] = tf32_rna_f(s_out[c][j2]);
    }
}

// ---------------- kernel 2: split-K tf32 HMMA GEMM, software-pipelined phases ------
// All 16 warps both premix and MMA. Iteration it: STS chunk it+1 -> buf[(it+1)&1],
// LDG prefetch chunk it+2, MMA chunk it from buf[it&1]. One syncthreads at loop end.
__global__ void __launch_bounds__(512, 1)
k_gemm(const __grid_constant__ CUtensorMap tmap_b,
       const float* __restrict__ adj,
       const float* __restrict__ att) {
    extern __shared__ __align__(1024) char dsm[];
    __shared__ __align__(8) uint64_t bars[2 * STAGES_B];

    const int tid  = threadIdx.x;
    const int wid  = tid >> 5;
    const int lane = tid & 31;
    const int g    = lane >> 2;
    const int q    = lane & 3;
    const int m0   = blockIdx.x * 128;
    const int sidx = blockIdx.y;

    const uint32_t dbase   = (smem_u32(dsm) + 1023u) & ~1023u;
    const uint32_t mixbase = dbase + STAGES_B * BTILE_BYTES;
    const uint32_t Bfull   = smem_u32(bars);
    const uint32_t Bempty  = Bfull + 8 * STAGES_B;

    if (tid == 0) {
        for (int s = 0; s < STAGES_B; ++s) {
            MBARRIER_INIT(Bfull + 8 * s, 1);
            MBARRIER_INIT(Bempty + 8 * s, 512);   // ALL threads arrive (fixes R6 count bug)
        }
        asm volatile("fence.proxy.async.shared::cta;" ::: "memory");
    }
    __syncthreads();

    const float at0 = att[0], at1 = att[1], at2 = att[2];
    const int nch = (NCHUNK - sidx + NSPLIT - 1) / NSPLIT;

    // ---- B TMA prologue ----
    if (tid == 0) {
        const int pre = (nch < STAGES_B) ? nch : STAGES_B;
        for (int i = 0; i < pre; ++i) {
            MBARRIER_EXPECT_TX(Bfull + 8 * i, (uint32_t)BTILE_BYTES);
            TMA_LOAD_3D(dbase + i * BTILE_BYTES, &tmap_b,
                        (sidx + i * NSPLIT) * KCH, 0, 0, Bfull + 8 * i);
        }
    }

    // premix mapping: 4 threads per row; thread owns one 8-k block h2 of row r
    const int r  = tid >> 2;
    const int h2 = tid & 3;
    const int mrow = (m0 + r < NN) ? (m0 + r) : (NN - 1);
    const float* arow = adj + (size_t)mrow * NN + 8 * h2;
    const uint32_t sbase = (uint32_t)r * 32 + (uint32_t)(((h2 + r) & 3) << 3);
    const uint32_t srot  = (uint32_t)(2 * r);

    const int wm = wid & 3;
    const int wn = wid >> 2;

    float acc[2][4][4];
    #pragma unroll
    for (int mi = 0; mi < 2; ++mi)
        #pragma unroll
        for (int ni = 0; ni < 4; ++ni)
            #pragma unroll
            for (int rr = 0; rr < 4; ++rr) acc[mi][ni][rr] = 0.f;

    float4 pf[NADJ][2];

    // ---- prologue: chunk 0 -> buf0; prefetch chunk 1 ----
    {
        const int k0 = sidx * KCH;
        const bool ok = (k0 + 8 * h2 + 8 <= NN);
        #pragma unroll
        for (int t = 0; t < NADJ; ++t) {
            const float* p0 = arow + (size_t)t * NN * NN + k0;
            pf[t][0] = ok ? *reinterpret_cast<const float4*>(p0)     : make_float4(0.f,0.f,0.f,0.f);
            pf[t][1] = ok ? *reinterpret_cast<const float4*>(p0 + 4) : make_float4(0.f,0.f,0.f,0.f);
        }
        float mv[8];
        #pragma unroll
        for (int i = 0; i < 8; ++i) {
            const float x = (&pf[0][i >> 2].x)[i & 3];
            const float y = (&pf[1][i >> 2].x)[i & 3];
            const float z = (&pf[2][i >> 2].x)[i & 3];
            mv[i] = fmaf(at2, z, fmaf(at1, y, at0 * x));
        }
        #pragma unroll
        for (int p = 0; p < 4; ++p)
            sts_b64(mixbase + (sbase + ((srot + 2 * (uint32_t)p) & 6)) * 4,
                    f2tf32(mv[p]), f2tf32(mv[p + 4]));
        if (nch > 1) {
            const int k1 = (sidx + NSPLIT) * KCH;
            const bool ok1 = (k1 + 8 * h2 + 8 <= NN);
            #pragma unroll
            for (int t = 0; t < NADJ; ++t) {
                const float* p0 = arow + (size_t)t * NN * NN + k1;
                pf[t][0] = ok1 ? *reinterpret_cast<const float4*>(p0)     : make_float4(0.f,0.f,0.f,0.f);
                pf[t][1] = ok1 ? *reinterpret_cast<const float4*>(p0 + 4) : make_float4(0.f,0.f,0.f,0.f);
            }
        }
    }
    __syncthreads();

    for (int it = 0; it < nch; ++it) {
        const int s = it & (STAGES_B - 1);
        const uint32_t mixcur = mixbase + (uint32_t)(it & 1) * MIX_BYTES;

        // ---- premix + STS chunk it+1 into the other buffer (overlaps MMA below) ----
        if (it + 1 < nch) {
            const uint32_t mixnext = mixbase + (uint32_t)((it + 1) & 1) * MIX_BYTES;
            float mv[8];
            #pragma unroll
            for (int i = 0; i < 8; ++i) {
                const float x = (&pf[0][i >> 2].x)[i & 3];
                const float y = (&pf[1][i >> 2].x)[i & 3];
                const float z = (&pf[2][i >> 2].x)[i & 3];
                mv[i] = fmaf(at2, z, fmaf(at1, y, at0 * x));
            }
            #pragma unroll
            for (int p = 0; p < 4; ++p)
                sts_b64(mixnext + (sbase + ((srot + 2 * (uint32_t)p) & 6)) * 4,
                        f2tf32(mv[p]), f2tf32(mv[p + 4]));
            // prefetch chunk it+2
            if (it + 2 < nch) {
                const int k0n = (sidx + (it + 2) * NSPLIT) * KCH;
                const bool ok = (k0n + 8 * h2 + 8 <= NN);
                #pragma unroll
                for (int t = 0; t < NADJ; ++t) {
                    const float* p0 = arow + (size_t)t * NN * NN + k0n;
                    pf[t][0] = ok ? *reinterpret_cast<const float4*>(p0)     : make_float4(0.f,0.f,0.f,0.f);
                    pf[t][1] = ok ? *reinterpret_cast<const float4*>(p0 + 4) : make_float4(0.f,0.f,0.f,0.f);
                }
            }
        }

        // ---- MMA chunk it ----
        MBARRIER_WAIT_PARITY(Bfull + 8 * s, (it / STAGES_B) & 1);
        const uint32_t Bb = dbase + s * BTILE_BYTES;

        #pragma unroll
        for (int ks = 0; ks < 4; ++ks) {
            const uint32_t koff = (uint32_t)(((((ks + g) & 3) << 3)) | ((2 * q + 2 * g) & 6));
            uint32_t amix[2][4];
            #pragma unroll
            for (int mi = 0; mi < 2; ++mi) {
                const uint32_t wa = ((uint32_t)(wm * 32 + mi * 16 + g) * 32) + koff;
                lds_b64(mixcur + wa * 4,         amix[mi][0], amix[mi][2]);
                lds_b64(mixcur + (wa + 256) * 4, amix[mi][1], amix[mi][3]);
            }
            const uint32_t kb = koff ^ ((uint32_t)g << 2);
            #pragma unroll
            for (int ni = 0; ni < 4; ++ni) {
                const uint32_t wb = ((uint32_t)(wn * 32 + ni * 8 + g) * 32) + kb;
                uint32_t b0, b1;
                lds_b64(Bb + wb * 4, b0, b1);
                mma_tf32(acc[0][ni], amix[0], b0, b1);
                mma_tf32(acc[1][ni], amix[1], b0, b1);
            }
        }

        MBARRIER_ARRIVE(Bempty + 8 * s);

        if (tid == 0 && it + STAGES_B < nch) {
            MBARRIER_WAIT_PARITY_RELAXED(Bempty + 8 * s, (it / STAGES_B) & 1);
            MBARRIER_EXPECT_TX(Bfull + 8 * s, (uint32_t)BTILE_BYTES);
            TMA_LOAD_3D(Bb, &tmap_b, (sidx + (it + STAGES_B) * NSPLIT) * KCH, 0, 0, Bfull + 8 * s);
        }

        __syncthreads();   // STS(it+1) complete; MMA(it) reads done before STS(it+2)
    }

    // ---- write split-K partials ----
    float* pbase = &g_part[sidx][0][0];
    #pragma unroll
    for (int mi = 0; mi < 2; ++mi) {
        #pragma unroll
        for (int ni = 0; ni < 4; ++ni) {
            const int rr = m0 + wm * 32 + mi * 16 + g;
            const int c  = wn * 32 + ni * 8 + q * 2;
            float2 v0 = make_float2(acc[mi][ni][0], acc[mi][ni][1]);
            float2 v1 = make_float2(acc[mi][ni][2], acc[mi][ni][3]);
            *reinterpret_cast<float2*>(pbase + (size_t)rr * CC + c)       = v0;
            *reinterpret_cast<float2*>(pbase + (size_t)(rr + 8) * CC + c) = v1;
        }
    }
}

// ---------------- kernel 3: reduce split-K partials + LeakyReLU --------------------
__global__ void __launch_bounds__(256)
k_reduce(float* __restrict__ out) {
    const int idx = blockIdx.x * 256 + threadIdx.x;
    const int total = NN * CC / 4;
    if (idx >= total) return;
    const int n  = idx / (CC / 4);
    const int c4 = (idx % (CC / 4)) * 4;

    float4 s = make_float4(0.f, 0.f, 0.f, 0.f);
    #pragma unroll
    for (int k = 0; k < NSPLIT; ++k) {
        const float4 v = *reinterpret_cast<const float4*>(&g_part[k][n][c4]);
        s.x += v.x; s.y += v.y; s.z += v.z; s.w += v.w;
    }
    s.x = (s.x >= 0.f) ? s.x : NSLOPE * s.x;
    s.y = (s.y >= 0.f) ? s.y : NSLOPE * s.y;
    s.z = (s.z >= 0.f) ? s.z : NSLOPE * s.z;
    s.w = (s.w >= 0.f) ? s.w : NSLOPE * s.w;
    *reinterpret_cast<float4*>(&out[(size_t)n * CC + c4]) = s;
}

// dummies: position k_gemm as 4th launch (6th overall) so ncu -s 5 -c 1 profiles it
__global__ void k_dummy() {}
__global__ void k_dummy2() {}

// ---------------- host launch ----------------
typedef CUresult (*PFN_encodeTiled)(
    CUtensorMap*, CUtensorMapDataType, cuuint32_t, void*,
    const cuuint64_t*, const cuuint64_t*, const cuuint32_t*, const cuuint32_t*,
    CUtensorMapInterleave, CUtensorMapSwizzle, CUtensorMapL2promotion,
    CUtensorMapFloatOOBfill);

extern "C" void kernel_launch(void* const* d_in, const int* in_sizes, int n_in,
                              void* d_out, int out_size) {
    const float *inp = nullptr, *adj = nullptr, *att = nullptr, *w = nullptr, *b = nullptr;
    for (int i = 0; i < n_in; ++i) {
        switch (in_sizes[i]) {
            case NN * CC:        inp = (const float*)d_in[i]; break;
            case NADJ * NN * NN: adj = (const float*)d_in[i]; break;
            case NADJ:           att = (const float*)d_in[i]; break;
            case CC * CC:        w   = (const float*)d_in[i]; break;
            case CC:             b   = (const float*)d_in[i]; break;
            default: break;
        }
    }
    float* out = (float*)d_out;

    k_support<<<NN / 8, 128>>>(inp, w, b);
    k_dummy<<<1, 32>>>();
    k_dummy2<<<1, 32>>>();

    PFN_encodeTiled enc = nullptr;
    {
        void* p = nullptr;
        cudaDriverEntryPointQueryResult st;
#if CUDART_VERSION >= 12050
        cudaGetDriverEntryPointByVersion("cuTensorMapEncodeTiled", &p, 12000,
                                         cudaEnableDefault, &st);
#else
        cudaGetDriverEntryPoint("cuTensorMapEncodeTiled", &p, cudaEnableDefault, &st);
#endif
        enc = (PFN_encodeTiled)p;
    }
    void* supt_ptr = nullptr;
    cudaGetSymbolAddress(&supt_ptr, g_sup_t);

    CUtensorMap tb;
    cuuint32_t box[3] = {KCH, 128, 1};
    cuuint32_t es[3]  = {1, 1, 1};
    {   // B: g_sup_t [CC][NPAD] (rotated layout), inner dim = K
        cuuint64_t dims[3] = {NPAD, CC, 1};
        cuuint64_t str[2]  = {(cuuint64_t)NPAD * 4, (cuuint64_t)CC * NPAD * 4};
        enc(&tb, CU_TENSOR_MAP_DATA_TYPE_FLOAT32, 3, supt_ptr, dims, str, box, es,
            CU_TENSOR_MAP_INTERLEAVE_NONE, CU_TENSOR_MAP_SWIZZLE_128B,
            CU_TENSOR_MAP_L2_PROMOTION_L2_128B, CU_TENSOR_MAP_FLOAT_OOB_FILL_NONE);
    }

    cudaFuncSetAttribute(k_gemm, cudaFuncAttributeMaxDynamicSharedMemorySize, DYNSMEM);
    dim3 grid(MTILES, NSPLIT);
    k_gemm<<<grid, 512, DYNSMEM>>>(tb, adj, att);

    k_reduce<<<(NN * CC / 4 + 255) / 256, 256>>>(out);
}

// round 9
// speedup vs baseline: 1.7522x; 1.0801x over previous
#include <cuda_runtime.h>
#include <cuda.h>
#include <cstdint>

// ---------------- problem constants ----------------
#define NN     10000
#define CC     128
#define NADJ   3
#define NSLOPE 0.2f

#define KCH     32
#define NCHUNK  ((NN + KCH - 1) / KCH)      // 313
#define NSPLIT  11
#define MTILES  ((NN + 127) / 128)          // 79
#define MPAD    (MTILES * 128)
#define WPR     (NCHUNK * 16)               // 5008 uint32 words per channel row (fp16 pairs)

#define BTILE_BYTES 8192                    // 128 c-rows x 16 words (fp16 halves)
#define STAGES_B    4
#define MIX_BYTES   8192                    // 128 m-rows x 16 words
#define DYNSMEM     (STAGES_B * BTILE_BYTES + 2 * MIX_BYTES + 1024)

// scratch (static device arrays — zero-initialized, no allocation)
__device__ __align__(1024) uint32_t g_sup_w[CC * WPR];         // supᵀ fp16, permuted+rotated
__device__ __align__(16)   float g_part[NSPLIT][MPAD][CC];     // split-K partials

// ---------------- helpers ----------------
__device__ __forceinline__ uint32_t smem_u32(const void* p) {
    uint32_t a;
    asm("{ .reg .u64 t; cvta.to.shared.u64 t, %1; cvt.u32.u64 %0, t; }" : "=r"(a) : "l"(p));
    return a;
}
// pack two fp32 -> fp16x2 (lo = first arg)
__device__ __forceinline__ uint32_t h2pack(float lo, float hi) {
    uint32_t d;
    asm("cvt.rn.f16x2.f32 %0, %1, %2;" : "=r"(d) : "f"(hi), "f"(lo));
    return d;
}
__device__ __forceinline__ void lds_b64(uint32_t a, uint32_t& lo, uint32_t& hi) {
    asm volatile("ld.shared.v2.b32 {%0, %1}, [%2];" : "=r"(lo), "=r"(hi) : "r"(a));
}
__device__ __forceinline__ void sts_b128(uint32_t a, uint32_t r0, uint32_t r1,
                                         uint32_t r2, uint32_t r3) {
    asm volatile("st.shared.v4.b32 [%0], {%1, %2, %3, %4};"
        :: "r"(a), "r"(r0), "r"(r1), "r"(r2), "r"(r3) : "memory");
}

#define MBARRIER_INIT(addr, cnt) \
    asm volatile("mbarrier.init.shared.b64 [%0], %1;" :: "r"(addr), "r"(cnt) : "memory")
#define MBARRIER_EXPECT_TX(addr, bytes) \
    asm volatile("mbarrier.arrive.expect_tx.shared.b64 _, [%0], %1;" :: "r"(addr), "r"(bytes) : "memory")
#define MBARRIER_ARRIVE(addr) \
    asm volatile("mbarrier.arrive.shared.b64 _, [%0];" :: "r"(addr) : "memory")

#define MBARRIER_WAIT_PARITY(mbar, par) do {                                      \
    uint32_t _m = (mbar), _p = (par), _d;                                         \
    asm volatile("{\n\t.reg .pred p;\n\t"                                         \
        "mbarrier.try_wait.parity.acquire.cta.shared::cta.b64 p, [%1], %2;\n\t"   \
        "selp.b32 %0, 1, 0, p;\n\t}" : "=r"(_d) : "r"(_m), "r"(_p) : "memory");   \
    if (!_d) {                                                                    \
        asm volatile("{\n\t.reg .pred P1;\n\t"                                    \
            "W_%=:\n\t"                                                           \
            "mbarrier.try_wait.parity.acquire.cta.shared::cta.b64 P1, [%0], %1, 0x989680;\n\t" \
            "@P1 bra.uni D_%=;\n\t"                                               \
            "bra.uni W_%=;\n\t"                                                   \
            "D_%=:\n\t}" :: "r"(_m), "r"(_p) : "memory");                         \
    } } while (0)

#define MBARRIER_WAIT_PARITY_RELAXED(mbar, par) do {                              \
    uint32_t _m = (mbar), _p = (par), _d;                                         \
    asm volatile("{\n\t.reg .pred p;\n\t"                                         \
        "mbarrier.try_wait.parity.relaxed.cta.shared::cta.b64 p, [%1], %2, 0x989680;\n\t" \
        "selp.b32 %0, 1, 0, p;\n\t}" : "=r"(_d) : "r"(_m), "r"(_p) : "memory");   \
    if (!_d) {                                                                    \
        asm volatile("{\n\t.reg .pred P1;\n\t"                                    \
            "W_%=:\n\t"                                                           \
            "mbarrier.try_wait.parity.relaxed.cta.shared::cta.b64 P1, [%0], %1, 0x989680;\n\t" \
            "@P1 bra.uni D_%=;\n\t"                                               \
            "bra.uni W_%=;\n\t"                                                   \
            "D_%=:\n\t}" :: "r"(_m), "r"(_p) : "memory");                         \
    } } while (0)

#define TMA_LOAD_3D(sa, tmap, x, y, z, mbar)                                      \
    asm volatile("cp.async.bulk.tensor.3d.shared::cta.global.tile.mbarrier::complete_tx::bytes " \
        "[%0], [%1, {%2, %3, %4}], [%5];"                                         \
        :: "r"((uint32_t)(sa)), "l"(tmap), "r"((int)(x)), "r"((int)(y)),          \
           "r"((int)(z)), "r"((uint32_t)(mbar)) : "memory")

// mma.sync m16n8k16 f16 with fp32 accumulate (baseline PTX, sm_80+)
__device__ __forceinline__ void mma_f16(float* c, const uint32_t* A,
                                        uint32_t b0, uint32_t b1) {
    asm volatile(
        "mma.sync.aligned.m16n8k16.row.col.f32.f16.f16.f32 "
        "{%0,%1,%2,%3}, {%4,%5,%6,%7}, {%8,%9}, {%0,%1,%2,%3};"
        : "+f"(c[0]), "+f"(c[1]), "+f"(c[2]), "+f"(c[3])
        : "r"(A[0]), "r"(A[1]), "r"(A[2]), "r"(A[3]), "r"(b0), "r"(b1));
}

// Layout (per 32-k chunk = 16 uint32 words, per row, both A-mix and B):
//   blocks j=0..3 of 4 words; block j stored at pos ((j+row)&3)*4.
//   block content: j<2: (w_{2j}, w_{2j+4}, w_{2j+1}, w_{2j+5});
//                  j>=2: same with +8 word offset (second k16 step).
//   Consumer thread q, k-step ks2: pair (w_{8ks2+q}, w_{8ks2+q+4}) is one LDS.64 at
//   block (2ks2 + (q>>1)), inner (q&1)*2.   word w holds halves k=2w, 2w+1.

// ---------------- kernel 1: support = X@W + b ; fp16 permuted transposed copy ------
__global__ void __launch_bounds__(128)
k_support(const float* __restrict__ inp, const float* __restrict__ w,
          const float* __restrict__ b) {
    __shared__ float in_s[8][CC];
    __shared__ float s_out[CC][9];
    const int t  = threadIdx.x;
    const int n0 = blockIdx.x * 8;

    #pragma unroll
    for (int j = 0; j < 8; ++j)
        in_s[j][t] = inp[(n0 + j) * CC + t];
    __syncthreads();

    float acc[8];
    #pragma unroll
    for (int j = 0; j < 8; ++j) acc[j] = 0.f;
    const float bc = b[t];
    #pragma unroll 4
    for (int i = 0; i < CC; ++i) {
        const float wv = w[i * CC + t];
        #pragma unroll
        for (int j = 0; j < 8; ++j) acc[j] = fmaf(in_s[j][i], wv, acc[j]);
    }
    #pragma unroll
    for (int j = 0; j < 8; ++j) s_out[t][j] = acc[j] + bc;
    __syncthreads();

    // store phase: thread (c0 = t>>2, w4 = t&3) packs nodes (2w4, 2w4+1) of this 8-group
    const int w4    = t & 3;
    const int c0    = t >> 2;              // 32 channels per pass
    const int chunk = n0 >> 5;
    const int wbase = (n0 & 31) >> 1;      // {0,4,8,12}
    const int wg    = wbase + w4;          // word index within chunk, 0..15
    const int jblk  = ((wg >> 3) << 1) | ((wg >> 1) & 1);
    const int r4    = wg & 7;
    const int inner = (r4 & 1) * 2 + (r4 >> 2);
    #pragma unroll
    for (int cc = 0; cc < CC; cc += 32) {
        const int c = cc + c0;
        const int pos = (((jblk + c) & 3) << 2) | inner;
        g_sup_w[(size_t)c * WPR + chunk * 16 + pos] =
            h2pack(s_out[c][2 * w4], s_out[c][2 * w4 + 1]);
    }
}

// ---------------- kernel 2: split-K fp16 HMMA GEMM, pipelined, fp16 tiles ----------
__global__ void __launch_bounds__(512, 1)
k_gemm(const __grid_constant__ CUtensorMap tmap_b,
       const float* __restrict__ adj,
       const float* __restrict__ att) {
    extern __shared__ __align__(1024) char dsm[];
    __shared__ __align__(8) uint64_t bars[2 * STAGES_B];

    const int tid  = threadIdx.x;
    const int wid  = tid >> 5;
    const int lane = tid & 31;
    const int g    = lane >> 2;
    const int q    = lane & 3;
    const int m0   = blockIdx.x * 128;
    const int sidx = blockIdx.y;

    const uint32_t dbase   = (smem_u32(dsm) + 1023u) & ~1023u;
    const uint32_t mixbase = dbase + STAGES_B * BTILE_BYTES;
    const uint32_t Bfull   = smem_u32(bars);
    const uint32_t Bempty  = Bfull + 8 * STAGES_B;

    if (tid == 0) {
        for (int s = 0; s < STAGES_B; ++s) {
            MBARRIER_INIT(Bfull + 8 * s, 1);
            MBARRIER_INIT(Bempty + 8 * s, 512);
        }
        asm volatile("fence.proxy.async.shared::cta;" ::: "memory");
    }
    __syncthreads();

    const float at0 = att[0], at1 = att[1], at2 = att[2];
    const int nch = (NCHUNK - sidx + NSPLIT - 1) / NSPLIT;

    // ---- B TMA prologue ----
    if (tid == 0) {
        const int pre = (nch < STAGES_B) ? nch : STAGES_B;
        for (int i = 0; i < pre; ++i) {
            MBARRIER_EXPECT_TX(Bfull + 8 * i, (uint32_t)BTILE_BYTES);
            TMA_LOAD_3D(dbase + i * BTILE_BYTES, &tmap_b,
                        (sidx + i * NSPLIT) * 16, 0, 0, Bfull + 8 * i);
        }
    }

    // producer mapping: 4 threads/row; thread j owns block j (8 k-values)
    const int r  = tid >> 2;
    const int j  = tid & 3;
    const int mrow = (m0 + r < NN) ? (m0 + r) : (NN - 1);
    const int off1 = ((j & 1) << 2) + ((j >> 1) << 4);   // {0,4,16,20}
    const int off2 = off1 + 8;                            // {8,12,24,28}
    const float* arow = adj + (size_t)mrow * NN;
    const uint32_t sts_addr_off = ((uint32_t)r * 16 + (uint32_t)(((j + r) & 3) << 2)) * 4;

    const int wm = wid & 3;
    const int wn = wid >> 2;

    float acc[2][4][4];
    #pragma unroll
    for (int mi = 0; mi < 2; ++mi)
        #pragma unroll
        for (int ni = 0; ni < 4; ++ni)
            #pragma unroll
            for (int rr = 0; rr < 4; ++rr) acc[mi][ni][rr] = 0.f;

    float4 pfa[NADJ], pfb[NADJ];

    // ---- prologue: premix chunk 0 -> buf0; prefetch chunk 1 ----
    {
        const int k0 = sidx * KCH;
        const bool ok1 = (k0 + off1 + 4 <= NN), ok2 = (k0 + off2 + 4 <= NN);
        #pragma unroll
        for (int t = 0; t < NADJ; ++t) {
            const float* p0 = arow + (size_t)t * NN * NN + k0;
            pfa[t] = ok1 ? *reinterpret_cast<const float4*>(p0 + off1) : make_float4(0.f,0.f,0.f,0.f);
            pfb[t] = ok2 ? *reinterpret_cast<const float4*>(p0 + off2) : make_float4(0.f,0.f,0.f,0.f);
        }
        float4 ma, mb;
        ma.x = fmaf(at2, pfa[2].x, fmaf(at1, pfa[1].x, at0 * pfa[0].x));
        ma.y = fmaf(at2, pfa[2].y, fmaf(at1, pfa[1].y, at0 * pfa[0].y));
        ma.z = fmaf(at2, pfa[2].z, fmaf(at1, pfa[1].z, at0 * pfa[0].z));
        ma.w = fmaf(at2, pfa[2].w, fmaf(at1, pfa[1].w, at0 * pfa[0].w));
        mb.x = fmaf(at2, pfb[2].x, fmaf(at1, pfb[1].x, at0 * pfb[0].x));
        mb.y = fmaf(at2, pfb[2].y, fmaf(at1, pfb[1].y, at0 * pfb[0].y));
        mb.z = fmaf(at2, pfb[2].z, fmaf(at1, pfb[1].z, at0 * pfb[0].z));
        mb.w = fmaf(at2, pfb[2].w, fmaf(at1, pfb[1].w, at0 * pfb[0].w));
        sts_b128(mixbase + sts_addr_off,
                 h2pack(ma.x, ma.y), h2pack(mb.x, mb.y),
                 h2pack(ma.z, ma.w), h2pack(mb.z, mb.w));
        if (nch > 1) {
            const int k1 = (sidx + NSPLIT) * KCH;
            const bool o1 = (k1 + off1 + 4 <= NN), o2 = (k1 + off2 + 4 <= NN);
            #pragma unroll
            for (int t = 0; t < NADJ; ++t) {
                const float* p0 = arow + (size_t)t * NN * NN + k1;
                pfa[t] = o1 ? *reinterpret_cast<const float4*>(p0 + off1) : make_float4(0.f,0.f,0.f,0.f);
                pfb[t] = o2 ? *reinterpret_cast<const float4*>(p0 + off2) : make_float4(0.f,0.f,0.f,0.f);
            }
        }
    }
    __syncthreads();

    for (int it = 0; it < nch; ++it) {
        const int s = it & (STAGES_B - 1);
        const uint32_t mixcur = mixbase + (uint32_t)(it & 1) * MIX_BYTES;

        // ---- premix + STS chunk it+1 (overlaps MMA below) ----
        if (it + 1 < nch) {
            const uint32_t mixnext = mixbase + (uint32_t)((it + 1) & 1) * MIX_BYTES;
            float4 ma, mb;
            ma.x = fmaf(at2, pfa[2].x, fmaf(at1, pfa[1].x, at0 * pfa[0].x));
            ma.y = fmaf(at2, pfa[2].y, fmaf(at1, pfa[1].y, at0 * pfa[0].y));
            ma.z = fmaf(at2, pfa[2].z, fmaf(at1, pfa[1].z, at0 * pfa[0].z));
            ma.w = fmaf(at2, pfa[2].w, fmaf(at1, pfa[1].w, at0 * pfa[0].w));
            mb.x = fmaf(at2, pfb[2].x, fmaf(at1, pfb[1].x, at0 * pfb[0].x));
            mb.y = fmaf(at2, pfb[2].y, fmaf(at1, pfb[1].y, at0 * pfb[0].y));
            mb.z = fmaf(at2, pfb[2].z, fmaf(at1, pfb[1].z, at0 * pfb[0].z));
            mb.w = fmaf(at2, pfb[2].w, fmaf(at1, pfb[1].w, at0 * pfb[0].w));
            sts_b128(mixnext + sts_addr_off,
                     h2pack(ma.x, ma.y), h2pack(mb.x, mb.y),
                     h2pack(ma.z, ma.w), h2pack(mb.z, mb.w));
            if (it + 2 < nch) {
                const int k0n = (sidx + (it + 2) * NSPLIT) * KCH;
                const bool o1 = (k0n + off1 + 4 <= NN), o2 = (k0n + off2 + 4 <= NN);
                #pragma unroll
                for (int t = 0; t < NADJ; ++t) {
                    const float* p0 = arow + (size_t)t * NN * NN + k0n;
                    pfa[t] = o1 ? *reinterpret_cast<const float4*>(p0 + off1) : make_float4(0.f,0.f,0.f,0.f);
                    pfb[t] = o2 ? *reinterpret_cast<const float4*>(p0 + off2) : make_float4(0.f,0.f,0.f,0.f);
                }
            }
        }

        // ---- MMA chunk it ----
        MBARRIER_WAIT_PARITY(Bfull + 8 * s, (it / STAGES_B) & 1);
        const uint32_t Bb = dbase + s * BTILE_BYTES;

        #pragma unroll
        for (int ks2 = 0; ks2 < 2; ++ks2) {
            const int blk = ks2 * 2 + (q >> 1);
            const uint32_t inn = (uint32_t)((q & 1) * 2);
            uint32_t amix[2][4];
            #pragma unroll
            for (int mi = 0; mi < 2; ++mi) {
                const int r0 = wm * 32 + mi * 16 + g;
                lds_b64(mixcur + ((uint32_t)r0 * 16 + (uint32_t)(((blk + r0) & 3) << 2) + inn) * 4,
                        amix[mi][0], amix[mi][2]);
                const int r1 = r0 + 8;
                lds_b64(mixcur + ((uint32_t)r1 * 16 + (uint32_t)(((blk + r1) & 3) << 2) + inn) * 4,
                        amix[mi][1], amix[mi][3]);
            }
            #pragma unroll
            for (int ni = 0; ni < 4; ++ni) {
                const int cn = wn * 32 + ni * 8 + g;
                uint32_t b0, b1;
                lds_b64(Bb + ((uint32_t)cn * 16 + (uint32_t)(((blk + cn) & 3) << 2) + inn) * 4,
                        b0, b1);
                mma_f16(acc[0][ni], amix[0], b0, b1);
                mma_f16(acc[1][ni], amix[1], b0, b1);
            }
        }

        MBARRIER_ARRIVE(Bempty + 8 * s);

        if (tid == 0 && it + STAGES_B < nch) {
            MBARRIER_WAIT_PARITY_RELAXED(Bempty + 8 * s, (it / STAGES_B) & 1);
            MBARRIER_EXPECT_TX(Bfull + 8 * s, (uint32_t)BTILE_BYTES);
            TMA_LOAD_3D(Bb, &tmap_b, (sidx + (it + STAGES_B) * NSPLIT) * 16, 0, 0, Bfull + 8 * s);
        }

        __syncthreads();
    }

    // ---- write split-K partials ----
    float* pbase = &g_part[sidx][0][0];
    #pragma unroll
    for (int mi = 0; mi < 2; ++mi) {
        #pragma unroll
        for (int ni = 0; ni < 4; ++ni) {
            const int rr = m0 + wm * 32 + mi * 16 + g;
            const int c  = wn * 32 + ni * 8 + q * 2;
            float2 v0 = make_float2(acc[mi][ni][0], acc[mi][ni][1]);
            float2 v1 = make_float2(acc[mi][ni][2], acc[mi][ni][3]);
            *reinterpret_cast<float2*>(pbase + (size_t)rr * CC + c)       = v0;
            *reinterpret_cast<float2*>(pbase + (size_t)(rr + 8) * CC + c) = v1;
        }
    }
}

// ---------------- kernel 3: reduce split-K partials + LeakyReLU --------------------
__global__ void __launch_bounds__(256)
k_reduce(float* __restrict__ out) {
    const int idx = blockIdx.x * 256 + threadIdx.x;
    const int total = NN * CC / 4;
    if (idx >= total) return;
    const int n  = idx / (CC / 4);
    const int c4 = (idx % (CC / 4)) * 4;

    float4 s = make_float4(0.f, 0.f, 0.f, 0.f);
    #pragma unroll
    for (int k = 0; k < NSPLIT; ++k) {
        const float4 v = *reinterpret_cast<const float4*>(&g_part[k][n][c4]);
        s.x += v.x; s.y += v.y; s.z += v.z; s.w += v.w;
    }
    s.x = (s.x >= 0.f) ? s.x : NSLOPE * s.x;
    s.y = (s.y >= 0.f) ? s.y : NSLOPE * s.y;
    s.z = (s.z >= 0.f) ? s.z : NSLOPE * s.z;
    s.w = (s.w >= 0.f) ? s.w : NSLOPE * s.w;
    *reinterpret_cast<float4*>(&out[(size_t)n * CC + c4]) = s;
}

// dummies: position k_gemm as 6th overall launch so ncu -s 5 -c 1 profiles it
__global__ void k_dummy() {}
__global__ void k_dummy2() {}

// ---------------- host launch ----------------
typedef CUresult (*PFN_encodeTiled)(
    CUtensorMap*, CUtensorMapDataType, cuuint32_t, void*,
    const cuuint64_t*, const cuuint64_t*, const cuuint32_t*, const cuuint32_t*,
    CUtensorMapInterleave, CUtensorMapSwizzle, CUtensorMapL2promotion,
    CUtensorMapFloatOOBfill);

extern "C" void kernel_launch(void* const* d_in, const int* in_sizes, int n_in,
                              void* d_out, int out_size) {
    const float *inp = nullptr, *adj = nullptr, *att = nullptr, *w = nullptr, *b = nullptr;
    for (int i = 0; i < n_in; ++i) {
        switch (in_sizes[i]) {
            case NN * CC:        inp = (const float*)d_in[i]; break;
            case NADJ * NN * NN: adj = (const float*)d_in[i]; break;
            case NADJ:           att = (const float*)d_in[i]; break;
            case CC * CC:        w   = (const float*)d_in[i]; break;
            case CC:             b   = (const float*)d_in[i]; break;
            default: break;
        }
    }
    float* out = (float*)d_out;

    k_support<<<NN / 8, 128>>>(inp, w, b);
    k_dummy<<<1, 32>>>();
    k_dummy2<<<1, 32>>>();

    PFN_encodeTiled enc = nullptr;
    {
        void* p = nullptr;
        cudaDriverEntryPointQueryResult st;
#if CUDART_VERSION >= 12050
        cudaGetDriverEntryPointByVersion("cuTensorMapEncodeTiled", &p, 12000,
                                         cudaEnableDefault, &st);
#else
        cudaGetDriverEntryPoint("cuTensorMapEncodeTiled", &p, cudaEnableDefault, &st);
#endif
        enc = (PFN_encodeTiled)p;
    }
    void* supw_ptr = nullptr;
    cudaGetSymbolAddress(&supw_ptr, g_sup_w);

    CUtensorMap tb;
    cuuint32_t box[3] = {16, 128, 1};      // 16 words (64B) x 128 channel rows
    cuuint32_t es[3]  = {1, 1, 1};
    {   // B: g_sup_w [CC][WPR] uint32 words, inner dim = words (permuted fp16 pairs)
        cuuint64_t dims[3] = {WPR, CC, 1};
        cuuint64_t str[2]  = {(cuuint64_t)WPR * 4, (cuuint64_t)CC * WPR * 4};
        enc(&tb, CU_TENSOR_MAP_DATA_TYPE_UINT32, 3, supw_ptr, dims, str, box, es,
            CU_TENSOR_MAP_INTERLEAVE_NONE, CU_TENSOR_MAP_SWIZZLE_NONE,
            CU_TENSOR_MAP_L2_PROMOTION_L2_128B, CU_TENSOR_MAP_FLOAT_OOB_FILL_NONE);
    }

    cudaFuncSetAttribute(k_gemm, cudaFuncAttributeMaxDynamicSharedMemorySize, DYNSMEM);
    dim3 grid(MTILES, NSPLIT);
    k_gemm<<<grid, 512, DYNSMEM>>>(tb, adj, att);

    k_reduce<<<(NN * CC / 4 + 255) / 256, 256>>>(out);
}